// round 15
// baseline (speedup 1.0000x reference)
#include <cuda_runtime.h>

// ---------------------------------------------------------------------------
// CustomCNN (LeNet-like), batch 8192, sm_100a.
// Channel-collapse identity => conv1(3->6)+tanh+mean+pool -> conv2sum(1->16)
// +tanh+mean+pool -> 25->120 dot -> fc1 -> fc2.
// R14/R15: two-kernel split. Kernel A = conv1+tanh+mean+pool (R13's hot
// loop, no serial tail) -> 6.4MB workspace. Kernel B = conv2..fc2 with 8
// images per CTA so every tail phase has >=200 active threads. Constant-
// memory weights, f32x2 FMA, tanh.approx in conv stack, accurate tanh head.
// (Resubmission after infra failure; workspace/guards/ordering audited.)
// ---------------------------------------------------------------------------

#define MAIN_THREADS 224
#define IMGS_B 8
typedef unsigned long long u64;

// Staging (written by prep_kernel), then copied into __constant__.
__device__ float g_w1s[600];        // conv1 repacked [(c,ky,kx)][8ch pad]
__device__ float g_k2s[400];        // conv2 channel-summed [tap][16ch]
__device__ float g_k3sT[25 * 120];  // conv3 channel-summed, transposed [i][o]

// Inter-kernel workspace: pooled conv1 output per image (196 floats).
__device__ float g_p1[8192 * 196];

// Constant tables (separate cache port; zero L1 wavefronts).
__constant__ __align__(16) ulonglong2 c_w1x[150];  // 75 taps x 8 floats
__constant__ __align__(16) ulonglong2 c_k2x[100];  // 25 taps x 16 floats

__device__ __forceinline__ u64 pack2(float lo, float hi) {
    u64 r; asm("mov.b64 %0, {%1,%2};" : "=l"(r) : "f"(lo), "f"(hi)); return r;
}
__device__ __forceinline__ void unpack2(u64 v, float& lo, float& hi) {
    asm("mov.b64 {%0,%1}, %2;" : "=f"(lo), "=f"(hi) : "l"(v));
}
__device__ __forceinline__ u64 ffma2(u64 a, u64 b, u64 c) {
    u64 d; asm("fma.rn.f32x2 %0, %1, %2, %3;" : "=l"(d) : "l"(a), "l"(b), "l"(c));
    return d;
}
// Accurate-ish tanh (head stages 5-6).
__device__ __forceinline__ float ftanh(float x) {
    x = fminf(fmaxf(x, -15.0f), 15.0f);
    float e = __expf(2.0f * x);
    return __fdividef(e - 1.0f, e + 1.0f);
}
// HW tanh (MUFU, 1 instr) — conv stack only; validated rel_err ~1e-5.
__device__ __forceinline__ float ftanh_hw(float x) {
    float y; asm("tanh.approx.f32 %0, %1;" : "=f"(y) : "f"(x)); return y;
}

__global__ void prep_kernel(const float* __restrict__ k1,
                            const float* __restrict__ k2,
                            const float* __restrict__ k3) {
    int t = threadIdx.x;
    if (t < 600) {
        int ch = t & 7;
        int rest = t >> 3;                 // (c*5+ky)*5+kx
        int c = rest / 25, ky = (rest % 25) / 5, kx = rest % 5;
        g_w1s[t] = (ch < 6) ? k1[((ch * 3 + c) * 5 + ky) * 5 + kx] : 0.f;
    }
    if (t < 400) {
        int i = t / 16, o = t % 16;
        float s = 0.f;
#pragma unroll
        for (int c = 0; c < 6; c++) s += k2[(o * 6 + c) * 25 + i];
        g_k2s[t] = s;
    }
    for (int idx = t; idx < 3000; idx += blockDim.x) {
        int i = idx / 120, o = idx % 120;
        float s = 0.f;
#pragma unroll
        for (int c = 0; c < 16; c++) s += k3[(o * 16 + c) * 25 + i];
        g_k3sT[idx] = s;
    }
}

// ========================== Kernel A: conv1 block ==========================
__global__ __launch_bounds__(MAIN_THREADS, 5)
void convA_kernel(const float* __restrict__ x, int batch) {
    __shared__ __align__(16) float s_img[2 * 3 * 32 * 36];  // rows padded to 36
    __shared__ float s_m1[2 * 28 * 28];

    const int tid = threadIdx.x;
    const int base = blockIdx.x * 2;
    const int nimg = (base + 2 <= batch) ? 2 : (batch - base);

    // stage 0: load images (row-padded)
    for (int v = 0; v < nimg; v++) {
        const float* xi = x + (size_t)(base + v) * 3072;
        float* si = s_img + v * 3456;
        for (int i = tid; i < 3072; i += MAIN_THREADS) {
            int c = i >> 10;
            int y = (i >> 5) & 31;
            int xc = i & 31;
            si[c * (32 * 36) + y * 36 + xc] = xi[i];
        }
    }
    __syncthreads();

    // stage 1: conv1 (3->6) + tanh + channel mean -> s_m1
    // 392 tasks, 2 strided passes; weights from __constant__.
#pragma unroll 1
    for (int pass = 0; pass < 2; pass++) {
        int q = tid + pass * MAIN_THREADS;
        if (q < 392) {
            int v = q / 196;
            if (v < nimg) {
                int t = q % 196;
                int row = t / 7;
                int x0 = (t % 7) * 4;
                const float* img = s_img + v * 3456;

                u64 acc[3][4];
#pragma unroll
                for (int p = 0; p < 3; p++)
#pragma unroll
                    for (int j = 0; j < 4; j++) acc[p][j] = 0ull;

#pragma unroll 1
                for (int c = 0; c < 3; c++) {
                    const float* cb = img + c * 1152;
#pragma unroll
                    for (int ky = 0; ky < 5; ky++) {
                        const float* rp = cb + (row + ky) * 36 + x0;
                        float4 a = *reinterpret_cast<const float4*>(rp);
                        float4 b = *reinterpret_cast<const float4*>(rp + 4);
                        u64 r8[8];
                        r8[0] = pack2(a.x, a.x); r8[1] = pack2(a.y, a.y);
                        r8[2] = pack2(a.z, a.z); r8[3] = pack2(a.w, a.w);
                        r8[4] = pack2(b.x, b.x); r8[5] = pack2(b.y, b.y);
                        r8[6] = pack2(b.z, b.z); r8[7] = pack2(b.w, b.w);

                        int tapB = (c * 5 + ky) * 5;
#pragma unroll
                        for (int kx = 0; kx < 5; kx++) {
                            ulonglong2 wAB = c_w1x[(tapB + kx) * 2];
                            u64 wC = c_w1x[(tapB + kx) * 2 + 1].x;
#pragma unroll
                            for (int j = 0; j < 4; j++) {
                                acc[0][j] = ffma2(r8[kx + j], wAB.x, acc[0][j]);
                                acc[1][j] = ffma2(r8[kx + j], wAB.y, acc[1][j]);
                                acc[2][j] = ffma2(r8[kx + j], wC,    acc[2][j]);
                            }
                        }
                    }
                }
                float m[4] = {0.f, 0.f, 0.f, 0.f};
#pragma unroll
                for (int p = 0; p < 3; p++)
#pragma unroll
                    for (int j = 0; j < 4; j++) {
                        float a0, a1;
                        unpack2(acc[p][j], a0, a1);
                        m[j] += ftanh_hw(a0) + ftanh_hw(a1);
                    }
#pragma unroll
                for (int j = 0; j < 4; j++)
                    s_m1[v * 784 + row * 28 + x0 + j] = m[j] * (1.0f / 6.0f);
            }
        }
    }
    __syncthreads();

    // stage 2: 2x2 avg pool -> workspace (coalesced STG)
    if (tid < 196) {
        int y = tid / 14, xx = tid % 14;
        for (int v = 0; v < nimg; v++) {
            const float* a = s_m1 + v * 784 + (2 * y) * 28 + 2 * xx;
            g_p1[(size_t)(base + v) * 196 + tid] =
                0.25f * (a[0] + a[1] + a[28] + a[29]);
        }
    }
}

// ====================== Kernel B: conv2..fc2 tail ==========================
__global__ __launch_bounds__(MAIN_THREADS)
void convB_kernel(const float* __restrict__ W1,
                  const float* __restrict__ b1,
                  const float* __restrict__ W2,
                  const float* __restrict__ b2,
                  float* __restrict__ out,
                  int batch) {
    __shared__ float s_p1[IMGS_B * 196];
    __shared__ float s_m2[IMGS_B * 100];
    __shared__ float s_p2[IMGS_B * 25];
    __shared__ float s_h3[IMGS_B * 120];
    __shared__ float s_f[IMGS_B * 84];

    const int tid = threadIdx.x;
    const int base = blockIdx.x * IMGS_B;
    const int nimg = (base + IMGS_B <= batch) ? IMGS_B : (batch - base);

    // load pooled maps (coalesced LDG)
    for (int i = tid; i < nimg * 196; i += MAIN_THREADS)
        s_p1[i] = g_p1[(size_t)base * 196 + i];
    __syncthreads();

    // stage 3: conv2sum (1->16) + tanh, constant weights
    for (int t = tid; t < nimg * 100; t += MAIN_THREADS) {
        int v = t / 100;
        int pix = t % 100;
        int y = pix / 10, xx = pix % 10;
        const float* p1 = s_p1 + v * 196;
        u64 acc[8];
#pragma unroll
        for (int p = 0; p < 8; p++) acc[p] = 0ull;
#pragma unroll
        for (int ky = 0; ky < 5; ky++) {
            const float* rp = p1 + (y + ky) * 14 + xx;
            u64 rb[5];
#pragma unroll
            for (int k = 0; k < 5; k++) {
                float val = rp[k];
                rb[k] = pack2(val, val);
            }
#pragma unroll
            for (int kx = 0; kx < 5; kx++) {
                int i = ky * 5 + kx;
                ulonglong2 w0 = c_k2x[i * 4];
                ulonglong2 w1 = c_k2x[i * 4 + 1];
                ulonglong2 w2 = c_k2x[i * 4 + 2];
                ulonglong2 w3 = c_k2x[i * 4 + 3];
                acc[0] = ffma2(rb[kx], w0.x, acc[0]);
                acc[1] = ffma2(rb[kx], w0.y, acc[1]);
                acc[2] = ffma2(rb[kx], w1.x, acc[2]);
                acc[3] = ffma2(rb[kx], w1.y, acc[3]);
                acc[4] = ffma2(rb[kx], w2.x, acc[4]);
                acc[5] = ffma2(rb[kx], w2.y, acc[5]);
                acc[6] = ffma2(rb[kx], w3.x, acc[6]);
                acc[7] = ffma2(rb[kx], w3.y, acc[7]);
            }
        }
        float s = 0.f;
#pragma unroll
        for (int p = 0; p < 8; p++) {
            float a0, a1;
            unpack2(acc[p], a0, a1);
            s += ftanh_hw(a0) + ftanh_hw(a1);
        }
        s_m2[t] = s;   // raw sum of 16 tanh
    }
    __syncthreads();

    // stage 4: channel-mean(/16) + 2x2 pool -> s_p2
    for (int t = tid; t < nimg * 25; t += MAIN_THREADS) {
        int v = t / 25;
        int q = t % 25;
        int y = q / 5, xx = q % 5;
        const float* mp = s_m2 + v * 100;
        float s = mp[(2 * y) * 10 + 2 * xx] + mp[(2 * y) * 10 + 2 * xx + 1] +
                  mp[(2 * y + 1) * 10 + 2 * xx] +
                  mp[(2 * y + 1) * 10 + 2 * xx + 1];
        s_p2[t] = s * (0.25f / 16.0f);
    }
    __syncthreads();

    // stage 5: k3sum dot (25->120) + tanh -> s_h3
    for (int t = tid; t < nimg * 120; t += MAIN_THREADS) {
        int v = t / 120;
        int o = t % 120;
        const float* p2 = s_p2 + v * 25;
        float a = 0.f;
#pragma unroll
        for (int i = 0; i < 25; i++) a += p2[i] * g_k3sT[i * 120 + o];
        s_h3[t] = ftanh(a);
    }
    __syncthreads();

    // stage 6: fc1 (120->84) + tanh
    for (int t = tid; t < nimg * 84; t += MAIN_THREADS) {
        int v = t / 84;
        int o = t % 84;
        const float* h3 = s_h3 + v * 120;
        float a = b1[o];
#pragma unroll 8
        for (int i = 0; i < 120; i++) a += h3[i] * W1[i * 84 + o];
        s_f[t] = ftanh(a);
    }
    __syncthreads();

    // stage 7: fc2 (84->10)
    for (int t = tid; t < nimg * 10; t += MAIN_THREADS) {
        int v = t / 10;
        int o = t % 10;
        const float* f = s_f + v * 84;
        float a = b2[o];
#pragma unroll
        for (int j = 0; j < 84; j++) a += f[j] * W2[j * 10 + o];
        out[(size_t)(base + v) * 10 + o] = a;
    }
}

extern "C" void kernel_launch(void* const* d_in, const int* in_sizes, int n_in,
                              void* d_out, int out_size) {
    const float* x  = (const float*)d_in[0];   // [B,3,32,32]
    const float* k1 = (const float*)d_in[1];   // [6,3,5,5]
    const float* k2 = (const float*)d_in[2];   // [16,6,5,5]
    const float* k3 = (const float*)d_in[3];   // [120,16,5,5]
    const float* W1 = (const float*)d_in[4];   // [120,84]
    const float* b1 = (const float*)d_in[5];   // [84]
    const float* W2 = (const float*)d_in[6];   // [84,10]
    const float* b2 = (const float*)d_in[7];   // [10]
    float* out = (float*)d_out;                // [B,10]

    int batch = in_sizes[0] / 3072;
    int blocksA = (batch + 1) / 2;
    int blocksB = (batch + IMGS_B - 1) / IMGS_B;

    prep_kernel<<<1, 640>>>(k1, k2, k3);

    // Publish staged weight tables to __constant__ (D2D async memcpys).
    void* p_w1s = nullptr;
    void* p_k2s = nullptr;
    cudaGetSymbolAddress(&p_w1s, g_w1s);
    cudaGetSymbolAddress(&p_k2s, g_k2s);
    cudaMemcpyToSymbolAsync(c_w1x, p_w1s, 600 * sizeof(float), 0,
                            cudaMemcpyDeviceToDevice, 0);
    cudaMemcpyToSymbolAsync(c_k2x, p_k2s, 400 * sizeof(float), 0,
                            cudaMemcpyDeviceToDevice, 0);

    convA_kernel<<<blocksA, MAIN_THREADS>>>(x, batch);
    convB_kernel<<<blocksB, MAIN_THREADS>>>(W1, b1, W2, b2, out, batch);
}

// round 16
// speedup vs baseline: 1.0906x; 1.0906x over previous
#include <cuda_runtime.h>

// ---------------------------------------------------------------------------
// CustomCNN (LeNet-like), batch 8192, sm_100a.
// Channel-collapse identity => conv1(3->6)+tanh+mean+pool -> conv2sum(1->16)
// +tanh+mean+pool -> 25->120 dot -> fc1 -> fc2.
// R16 = R15 two-kernel split with the fixed overhead removed:
//   - prep parallelized (16x256, was 1x640 @ 18.3us measured)
//   - single merged constant table + ONE memcpyToSymbolAsync (was two)
// Kernel A (conv1 block) and Kernel B (conv2..fc2, 8 img/CTA) unchanged.
// ---------------------------------------------------------------------------

#define MAIN_THREADS 224
#define IMGS_B 8
typedef unsigned long long u64;

// Staging (written by prep_kernel), then copied into __constant__ in ONE copy.
// Layout: [0..599] conv1 repacked [(c,ky,kx)][8ch pad], [600..999] conv2
// channel-summed transposed [tap][16ch].
__device__ float g_stage[1000];
__device__ float g_k3sT[25 * 120];  // conv3 channel-summed, transposed [i][o]

// Merged constant table (separate cache port; zero L1 wavefronts).
// c_tab[0..149]   : conv1 — tap t uses c_tab[2t] (ch01,ch23) and c_tab[2t+1].x (ch45)
// c_tab[150..249] : conv2 — tap i uses c_tab[150+4i .. 150+4i+3] (ch pairs 01..15)
__constant__ __align__(16) ulonglong2 c_tab[250];

__device__ __forceinline__ u64 pack2(float lo, float hi) {
    u64 r; asm("mov.b64 %0, {%1,%2};" : "=l"(r) : "f"(lo), "f"(hi)); return r;
}
__device__ __forceinline__ void unpack2(u64 v, float& lo, float& hi) {
    asm("mov.b64 {%0,%1}, %2;" : "=f"(lo), "=f"(hi) : "l"(v));
}
__device__ __forceinline__ u64 ffma2(u64 a, u64 b, u64 c) {
    u64 d; asm("fma.rn.f32x2 %0, %1, %2, %3;" : "=l"(d) : "l"(a), "l"(b), "l"(c));
    return d;
}
// Accurate-ish tanh (head stages 5-6).
__device__ __forceinline__ float ftanh(float x) {
    x = fminf(fmaxf(x, -15.0f), 15.0f);
    float e = __expf(2.0f * x);
    return __fdividef(e - 1.0f, e + 1.0f);
}
// HW tanh (MUFU, 1 instr) — conv stack only; validated rel_err ~1e-5.
__device__ __forceinline__ float ftanh_hw(float x) {
    float y; asm("tanh.approx.f32 %0, %1;" : "=f"(y) : "f"(x)); return y;
}

// Fully parallel prep: 4096 threads, one output element each.
__global__ void prep_kernel(const float* __restrict__ k1,
                            const float* __restrict__ k2,
                            const float* __restrict__ k3) {
    int idx = blockIdx.x * blockDim.x + threadIdx.x;
    if (idx < 600) {
        // conv1: k1 [o][c][ky][kx] -> g_stage[((c*5+ky)*5+kx)*8 + o], o>=6 zero.
        int ch = idx & 7;
        int rest = idx >> 3;               // (c*5+ky)*5+kx
        int c = rest / 25, ky = (rest % 25) / 5, kx = rest % 5;
        g_stage[idx] = (ch < 6) ? k1[((ch * 3 + c) * 5 + ky) * 5 + kx] : 0.f;
    } else if (idx < 1000) {
        // conv2: channel-sum, transposed [tap][16ch].
        int t = idx - 600;
        int i = t / 16, o = t % 16;
        float s = 0.f;
#pragma unroll
        for (int c = 0; c < 6; c++) s += k2[(o * 6 + c) * 25 + i];
        g_stage[idx] = s;
    } else if (idx < 4000) {
        // conv3: channel-sum, transposed [i][o].
        int t = idx - 1000;
        int i = t / 120, o = t % 120;
        float s = 0.f;
#pragma unroll
        for (int c = 0; c < 16; c++) s += k3[(o * 16 + c) * 25 + i];
        g_k3sT[t] = s;
    }
}

// ========================== Kernel A: conv1 block ==========================
__global__ __launch_bounds__(MAIN_THREADS, 5)
void convA_kernel(const float* __restrict__ x,
                  float* __restrict__ p1ws, int batch) {
    __shared__ __align__(16) float s_img[2 * 3 * 32 * 36];  // rows padded to 36
    __shared__ float s_m1[2 * 28 * 28];

    const int tid = threadIdx.x;
    const int base = blockIdx.x * 2;
    const int nimg = (base + 2 <= batch) ? 2 : (batch - base);

    // stage 0: load images (row-padded)
    for (int v = 0; v < nimg; v++) {
        const float* xi = x + (size_t)(base + v) * 3072;
        float* si = s_img + v * 3456;
        for (int i = tid; i < 3072; i += MAIN_THREADS) {
            int c = i >> 10;
            int y = (i >> 5) & 31;
            int xc = i & 31;
            si[c * (32 * 36) + y * 36 + xc] = xi[i];
        }
    }
    __syncthreads();

    // stage 1: conv1 (3->6) + tanh + channel mean -> s_m1
    // 392 tasks, 2 strided passes; weights from __constant__.
#pragma unroll 1
    for (int pass = 0; pass < 2; pass++) {
        int q = tid + pass * MAIN_THREADS;
        if (q < 392) {
            int v = q / 196;
            if (v < nimg) {
                int t = q % 196;
                int row = t / 7;
                int x0 = (t % 7) * 4;
                const float* img = s_img + v * 3456;

                u64 acc[3][4];
#pragma unroll
                for (int p = 0; p < 3; p++)
#pragma unroll
                    for (int j = 0; j < 4; j++) acc[p][j] = 0ull;

#pragma unroll 1
                for (int c = 0; c < 3; c++) {
                    const float* cb = img + c * 1152;
#pragma unroll
                    for (int ky = 0; ky < 5; ky++) {
                        const float* rp = cb + (row + ky) * 36 + x0;
                        float4 a = *reinterpret_cast<const float4*>(rp);
                        float4 b = *reinterpret_cast<const float4*>(rp + 4);
                        u64 r8[8];
                        r8[0] = pack2(a.x, a.x); r8[1] = pack2(a.y, a.y);
                        r8[2] = pack2(a.z, a.z); r8[3] = pack2(a.w, a.w);
                        r8[4] = pack2(b.x, b.x); r8[5] = pack2(b.y, b.y);
                        r8[6] = pack2(b.z, b.z); r8[7] = pack2(b.w, b.w);

                        int tapB = (c * 5 + ky) * 5;
#pragma unroll
                        for (int kx = 0; kx < 5; kx++) {
                            ulonglong2 wAB = c_tab[(tapB + kx) * 2];
                            u64 wC = c_tab[(tapB + kx) * 2 + 1].x;
#pragma unroll
                            for (int j = 0; j < 4; j++) {
                                acc[0][j] = ffma2(r8[kx + j], wAB.x, acc[0][j]);
                                acc[1][j] = ffma2(r8[kx + j], wAB.y, acc[1][j]);
                                acc[2][j] = ffma2(r8[kx + j], wC,    acc[2][j]);
                            }
                        }
                    }
                }
                float m[4] = {0.f, 0.f, 0.f, 0.f};
#pragma unroll
                for (int p = 0; p < 3; p++)
#pragma unroll
                    for (int j = 0; j < 4; j++) {
                        float a0, a1;
                        unpack2(acc[p][j], a0, a1);
                        m[j] += ftanh_hw(a0) + ftanh_hw(a1);
                    }
#pragma unroll
                for (int j = 0; j < 4; j++)
                    s_m1[v * 784 + row * 28 + x0 + j] = m[j] * (1.0f / 6.0f);
            }
        }
    }
    __syncthreads();

    // stage 2: 2x2 avg pool -> workspace (coalesced STG)
    if (tid < 196) {
        int y = tid / 14, xx = tid % 14;
        for (int v = 0; v < nimg; v++) {
            const float* a = s_m1 + v * 784 + (2 * y) * 28 + 2 * xx;
            p1ws[(size_t)(base + v) * 196 + tid] =
                0.25f * (a[0] + a[1] + a[28] + a[29]);
        }
    }
}

// Inter-kernel workspace: pooled conv1 output per image (196 floats).
__device__ float g_p1[8192 * 196];

// ====================== Kernel B: conv2..fc2 tail ==========================
__global__ __launch_bounds__(MAIN_THREADS)
void convB_kernel(const float* __restrict__ W1,
                  const float* __restrict__ b1,
                  const float* __restrict__ W2,
                  const float* __restrict__ b2,
                  float* __restrict__ out,
                  int batch) {
    __shared__ float s_p1[IMGS_B * 196];
    __shared__ float s_m2[IMGS_B * 100];
    __shared__ float s_p2[IMGS_B * 25];
    __shared__ float s_h3[IMGS_B * 120];
    __shared__ float s_f[IMGS_B * 84];

    const int tid = threadIdx.x;
    const int base = blockIdx.x * IMGS_B;
    const int nimg = (base + IMGS_B <= batch) ? IMGS_B : (batch - base);

    // load pooled maps (coalesced LDG)
    for (int i = tid; i < nimg * 196; i += MAIN_THREADS)
        s_p1[i] = g_p1[(size_t)base * 196 + i];
    __syncthreads();

    // stage 3: conv2sum (1->16) + tanh, constant weights
    for (int t = tid; t < nimg * 100; t += MAIN_THREADS) {
        int v = t / 100;
        int pix = t % 100;
        int y = pix / 10, xx = pix % 10;
        const float* p1 = s_p1 + v * 196;
        u64 acc[8];
#pragma unroll
        for (int p = 0; p < 8; p++) acc[p] = 0ull;
#pragma unroll
        for (int ky = 0; ky < 5; ky++) {
            const float* rp = p1 + (y + ky) * 14 + xx;
            u64 rb[5];
#pragma unroll
            for (int k = 0; k < 5; k++) {
                float val = rp[k];
                rb[k] = pack2(val, val);
            }
#pragma unroll
            for (int kx = 0; kx < 5; kx++) {
                int i = ky * 5 + kx;
                ulonglong2 w0 = c_tab[150 + i * 4];
                ulonglong2 w1 = c_tab[150 + i * 4 + 1];
                ulonglong2 w2 = c_tab[150 + i * 4 + 2];
                ulonglong2 w3 = c_tab[150 + i * 4 + 3];
                acc[0] = ffma2(rb[kx], w0.x, acc[0]);
                acc[1] = ffma2(rb[kx], w0.y, acc[1]);
                acc[2] = ffma2(rb[kx], w1.x, acc[2]);
                acc[3] = ffma2(rb[kx], w1.y, acc[3]);
                acc[4] = ffma2(rb[kx], w2.x, acc[4]);
                acc[5] = ffma2(rb[kx], w2.y, acc[5]);
                acc[6] = ffma2(rb[kx], w3.x, acc[6]);
                acc[7] = ffma2(rb[kx], w3.y, acc[7]);
            }
        }
        float s = 0.f;
#pragma unroll
        for (int p = 0; p < 8; p++) {
            float a0, a1;
            unpack2(acc[p], a0, a1);
            s += ftanh_hw(a0) + ftanh_hw(a1);
        }
        s_m2[t] = s;   // raw sum of 16 tanh
    }
    __syncthreads();

    // stage 4: channel-mean(/16) + 2x2 pool -> s_p2
    for (int t = tid; t < nimg * 25; t += MAIN_THREADS) {
        int v = t / 25;
        int q = t % 25;
        int y = q / 5, xx = q % 5;
        const float* mp = s_m2 + v * 100;
        float s = mp[(2 * y) * 10 + 2 * xx] + mp[(2 * y) * 10 + 2 * xx + 1] +
                  mp[(2 * y + 1) * 10 + 2 * xx] +
                  mp[(2 * y + 1) * 10 + 2 * xx + 1];
        s_p2[t] = s * (0.25f / 16.0f);
    }
    __syncthreads();

    // stage 5: k3sum dot (25->120) + tanh -> s_h3
    for (int t = tid; t < nimg * 120; t += MAIN_THREADS) {
        int v = t / 120;
        int o = t % 120;
        const float* p2 = s_p2 + v * 25;
        float a = 0.f;
#pragma unroll
        for (int i = 0; i < 25; i++) a += p2[i] * g_k3sT[i * 120 + o];
        s_h3[t] = ftanh(a);
    }
    __syncthreads();

    // stage 6: fc1 (120->84) + tanh
    for (int t = tid; t < nimg * 84; t += MAIN_THREADS) {
        int v = t / 84;
        int o = t % 84;
        const float* h3 = s_h3 + v * 120;
        float a = b1[o];
#pragma unroll 8
        for (int i = 0; i < 120; i++) a += h3[i] * W1[i * 84 + o];
        s_f[t] = ftanh(a);
    }
    __syncthreads();

    // stage 7: fc2 (84->10)
    for (int t = tid; t < nimg * 10; t += MAIN_THREADS) {
        int v = t / 10;
        int o = t % 10;
        const float* f = s_f + v * 84;
        float a = b2[o];
#pragma unroll
        for (int j = 0; j < 84; j++) a += f[j] * W2[j * 10 + o];
        out[(size_t)(base + v) * 10 + o] = a;
    }
}

extern "C" void kernel_launch(void* const* d_in, const int* in_sizes, int n_in,
                              void* d_out, int out_size) {
    const float* x  = (const float*)d_in[0];   // [B,3,32,32]
    const float* k1 = (const float*)d_in[1];   // [6,3,5,5]
    const float* k2 = (const float*)d_in[2];   // [16,6,5,5]
    const float* k3 = (const float*)d_in[3];   // [120,16,5,5]
    const float* W1 = (const float*)d_in[4];   // [120,84]
    const float* b1 = (const float*)d_in[5];   // [84]
    const float* W2 = (const float*)d_in[6];   // [84,10]
    const float* b2 = (const float*)d_in[7];   // [10]
    float* out = (float*)d_out;                // [B,10]

    int batch = in_sizes[0] / 3072;
    int blocksA = (batch + 1) / 2;
    int blocksB = (batch + IMGS_B - 1) / IMGS_B;

    // Parallel prep: 16 blocks x 256 threads, one element per thread.
    prep_kernel<<<16, 256>>>(k1, k2, k3);

    // Publish the merged weight table to __constant__ (ONE D2D async memcpy).
    void* p_stage = nullptr;
    cudaGetSymbolAddress(&p_stage, g_stage);
    cudaMemcpyToSymbolAsync(c_tab, p_stage, 1000 * sizeof(float), 0,
                            cudaMemcpyDeviceToDevice, 0);

    void* p_ws = nullptr;
    cudaGetSymbolAddress(&p_ws, g_p1);

    convA_kernel<<<blocksA, MAIN_THREADS>>>(x, (float*)p_ws, batch);
    convB_kernel<<<blocksB, MAIN_THREADS>>>(W1, b1, W2, b2, out, batch);
}